// round 11
// baseline (speedup 1.0000x reference)
#include <cuda_runtime.h>
#include <cstdint>
#include <math.h>

// GJR-GARCH(1,1):  h[t] = c[t] + beta*h[t-1],  h[0]=var(returns,ddof=1)
// c[t] = omega + (alpha + gamma*[r[t-1]<0]) * r[t-1]^2
// Output: [sqrt(h) | h], each N floats.
//
// R11: warp owns 1024 elems = 4 rounds of 256 (lane owns 8 floats = 2 float4).
// ALL 8 LDG.128 issued upfront (MLP 8, one exposed-latency phase per chunk),
// then one ILP-4 compute phase: c-transform + 8-deep local prefix (in-place),
// 4 interleaved B-only warp scans (m=beta^8, uniform step mults beta^(8d)),
// beta^256 carry chain, store phase. 128-term window carry. TPB=128,
// grid ~4096 blocks (~4 waves). Variance fused; last block folds h0 and
// recomputes outputs [0,1024).

#define WPB    4
#define TPB    (WPB * 32)        // 128
#define CHUNK  1024
#define BLK    (WPB * CHUNK)     // 4096 elements per block
#define NPART_MAX 32768
#define FULLMASK 0xffffffffu

__device__ float    g_ps[NPART_MAX];
__device__ float    g_pq[NPART_MAX];
__device__ unsigned g_done = 0;

__device__ __forceinline__ float sqrt_approx(float x) {
    float y; asm("sqrt.approx.f32 %0, %1;" : "=f"(y) : "f"(x)); return y;
}

// exact m^e for 0<=e<=31 from precomputed squarings
__device__ __forceinline__ float powk(float m1, float m2, float m4,
                                      float m8, float m16, int e) {
    float p = 1.f;
    if (e & 1)  p *= m1;
    if (e & 2)  p *= m2;
    if (e & 4)  p *= m4;
    if (e & 8)  p *= m8;
    if (e & 16) p *= m16;
    return p;
}

__global__ void __launch_bounds__(TPB) k_all(
    const float* __restrict__ r,
    const float* __restrict__ p_omega, const float* __restrict__ p_alpha,
    const float* __restrict__ p_beta,  const float* __restrict__ p_gamma,
    float* __restrict__ out, int n)
{
    const int tid  = threadIdx.x;
    const int w    = tid >> 5;
    const int lane = tid & 31;
    const int base = blockIdx.x * BLK + w * CHUNK;

    const float omega = __ldg(p_omega);
    const float alpha = __ldg(p_alpha);
    const float beta  = __ldg(p_beta);
    const float gamma = __ldg(p_gamma);
    const float ag = alpha + gamma;

    // powers of beta (exact squarings)
    const float bp1 = beta;
    const float bp2 = bp1 * bp1, bp4 = bp2 * bp2, bp8 = bp4 * bp4;
    const float bp16 = bp8 * bp8, bp32 = bp16 * bp16;
    const float bp64 = bp32 * bp32, bp128 = bp64 * bp64;
    const float bp256 = bp128 * bp128;
    const float b3 = bp1 * bp2;
    const float b5 = bp4 * bp1, b6 = bp4 * bp2, b7 = bp4 * b3;

    // per-lane constants
    const float bl4 = powk(bp4, bp8, bp16, bp32, bp64, lane);   // beta^(4*lane)
    const float bl8 = powk(bp8, bp16, bp32, bp64, bp128, lane); // beta^(8*lane)

    float s = 0.f, q = 0.f;

    if (base < n) {
        // ---- chunk carry-in Hc ~= h[base-1]: 128-term window (coalesced) ----
        float Hc = 0.f;
        if (base > 0) {
            float bj = powk(bp1, bp2, bp4, bp8, bp16, lane);   // beta^lane
            float P  = 0.f;
            const float* rb = r + base - 2 - lane;       // term j = 32*i + lane
            #pragma unroll
            for (int i = 0; i < 4; i++) {
                float rp   = rb[-32 * i];
                float coef = (rp < 0.f) ? ag : alpha;
                P  = fmaf(bj, fmaf(coef * rp, rp, omega), P);
                bj *= bp32;
            }
            #pragma unroll
            for (int d = 16; d; d >>= 1) P += __shfl_xor_sync(FULLMASK, P, d);
            Hc = P;
        }
        float rlast = (base > 0) ? __ldg(r + base - 1) : 0.f;

        if (base + CHUNK <= n && ((n & 3) == 0)) {
            // ====== fast path: all loads upfront (MLP 8), one compute phase ======
            const float4* r4  = (const float4*)(r + base);
            float4*       oh4 = (float4*)(out + n + base);
            float4*       os4 = (float4*)(out + base);

            // load phase: 8 x LDG.128
            float4 va[4], vb[4];
            #pragma unroll
            for (int i = 0; i < 4; i++) {
                va[i] = r4[i * 64 + 2 * lane];
                vb[i] = r4[i * 64 + 2 * lane + 1];
            }

            // variance partials
            #pragma unroll
            for (int i = 0; i < 4; i++) {
                s += ((va[i].x + va[i].y) + (va[i].z + va[i].w))
                   + ((vb[i].x + vb[i].y) + (vb[i].z + vb[i].w));
                q = fmaf(va[i].x, va[i].x, q); q = fmaf(va[i].y, va[i].y, q);
                q = fmaf(va[i].z, va[i].z, q); q = fmaf(va[i].w, va[i].w, q);
                q = fmaf(vb[i].x, vb[i].x, q); q = fmaf(vb[i].y, vb[i].y, q);
                q = fmaf(vb[i].z, vb[i].z, q); q = fmaf(vb[i].w, vb[i].w, q);
            }

            // previous-element for each lane's first slot, per round
            float rp0[4];
            {
                float t31[4];
                #pragma unroll
                for (int i = 0; i < 4; i++) {
                    rp0[i] = __shfl_up_sync(FULLMASK, vb[i].w, 1);
                    t31[i] = __shfl_sync(FULLMASK, vb[i].w, 31);
                }
                if (lane == 0) {
                    rp0[0] = rlast;
                    rp0[1] = t31[0];
                    rp0[2] = t31[1];
                    rp0[3] = t31[2];
                }
            }

            // c-transform + 8-deep local affine prefix, in place (va/vb -> p)
            #pragma unroll
            for (int i = 0; i < 4; i++) {
                float c0, c1, c2, c3, c4, c5, c6, c7;
                { float t = rp0[i];  float cf = (t < 0.f) ? ag : alpha; c0 = fmaf(cf * t, t, omega); }
                { float t = va[i].x; float cf = (t < 0.f) ? ag : alpha; c1 = fmaf(cf * t, t, omega); }
                { float t = va[i].y; float cf = (t < 0.f) ? ag : alpha; c2 = fmaf(cf * t, t, omega); }
                { float t = va[i].z; float cf = (t < 0.f) ? ag : alpha; c3 = fmaf(cf * t, t, omega); }
                { float t = va[i].w; float cf = (t < 0.f) ? ag : alpha; c4 = fmaf(cf * t, t, omega); }
                { float t = vb[i].x; float cf = (t < 0.f) ? ag : alpha; c5 = fmaf(cf * t, t, omega); }
                { float t = vb[i].y; float cf = (t < 0.f) ? ag : alpha; c6 = fmaf(cf * t, t, omega); }
                { float t = vb[i].z; float cf = (t < 0.f) ? ag : alpha; c7 = fmaf(cf * t, t, omega); }
                float p0 = c0;
                float p1 = fmaf(bp1, p0, c1);
                float p2 = fmaf(bp1, p1, c2);
                float p3 = fmaf(bp1, p2, c3);
                float p4 = fmaf(bp1, p3, c4);
                float p5 = fmaf(bp1, p4, c5);
                float p6 = fmaf(bp1, p5, c6);
                float p7 = fmaf(bp1, p6, c7);
                va[i].x = p0; va[i].y = p1; va[i].z = p2; va[i].w = p3;
                vb[i].x = p4; vb[i].y = p5; vb[i].z = p6; vb[i].w = p7;
            }

            // 4 interleaved B-only warp scans; m = beta^8, step d mult = m^d
            float B[4];
            #pragma unroll
            for (int i = 0; i < 4; i++) B[i] = vb[i].w;
            {
                float Bp[4];
                #pragma unroll
                for (int i = 0; i < 4; i++) Bp[i] = __shfl_up_sync(FULLMASK, B[i], 1);
                #pragma unroll
                for (int i = 0; i < 4; i++) if (lane >= 1) B[i] = fmaf(bp8, Bp[i], B[i]);
                #pragma unroll
                for (int i = 0; i < 4; i++) Bp[i] = __shfl_up_sync(FULLMASK, B[i], 2);
                #pragma unroll
                for (int i = 0; i < 4; i++) if (lane >= 2) B[i] = fmaf(bp16, Bp[i], B[i]);
                #pragma unroll
                for (int i = 0; i < 4; i++) Bp[i] = __shfl_up_sync(FULLMASK, B[i], 4);
                #pragma unroll
                for (int i = 0; i < 4; i++) if (lane >= 4) B[i] = fmaf(bp32, Bp[i], B[i]);
                #pragma unroll
                for (int i = 0; i < 4; i++) Bp[i] = __shfl_up_sync(FULLMASK, B[i], 8);
                #pragma unroll
                for (int i = 0; i < 4; i++) if (lane >= 8) B[i] = fmaf(bp64, Bp[i], B[i]);
                #pragma unroll
                for (int i = 0; i < 4; i++) Bp[i] = __shfl_up_sync(FULLMASK, B[i], 16);
                #pragma unroll
                for (int i = 0; i < 4; i++) if (lane >= 16) B[i] = fmaf(bp128, Bp[i], B[i]);
            }

            // exclusive value + totals, carry chain (one fma per round)
            float Bx[4], T[4];
            #pragma unroll
            for (int i = 0; i < 4; i++) {
                float bu = __shfl_up_sync(FULLMASK, B[i], 1);
                Bx[i] = (lane == 0) ? 0.f : bu;
                T[i]  = __shfl_sync(FULLMASK, B[i], 31);
            }
            float Hin[4];
            Hin[0] = Hc;
            Hin[1] = fmaf(bp256, Hin[0], T[0]);
            Hin[2] = fmaf(bp256, Hin[1], T[1]);
            Hin[3] = fmaf(bp256, Hin[2], T[2]);

            // apply carries + store phase
            #pragma unroll
            for (int i = 0; i < 4; i++) {
                float Hl = fmaf(bl8, Hin[i], Bx[i]);   // h[a-1] for this lane
                float h0v = fmaf(bp1, Hl, va[i].x);
                float h1v = fmaf(bp2, Hl, va[i].y);
                float h2v = fmaf(b3,  Hl, va[i].z);
                float h3v = fmaf(bp4, Hl, va[i].w);
                float h4v = fmaf(b5,  Hl, vb[i].x);
                float h5v = fmaf(b6,  Hl, vb[i].y);
                float h6v = fmaf(b7,  Hl, vb[i].z);
                float h7v = fmaf(bp8, Hl, vb[i].w);
                int idx = i * 64 + 2 * lane;
                __stcs(&oh4[idx],     make_float4(h0v, h1v, h2v, h3v));
                __stcs(&oh4[idx + 1], make_float4(h4v, h5v, h6v, h7v));
                __stcs(&os4[idx],
                       make_float4(sqrt_approx(h0v), sqrt_approx(h1v),
                                   sqrt_approx(h2v), sqrt_approx(h3v)));
                __stcs(&os4[idx + 1],
                       make_float4(sqrt_approx(h4v), sqrt_approx(h5v),
                                   sqrt_approx(h6v), sqrt_approx(h7v)));
            }
        } else {
            // =============== guarded scalar path (partial chunk) ===============
            #pragma unroll 1
            for (int j = 0; j < CHUNK / 128; j++) {
                int e0 = base + j * 128 + 4 * lane;
                float x0 = (e0 + 0 < n) ? r[e0 + 0] : 0.f;
                float x1 = (e0 + 1 < n) ? r[e0 + 1] : 0.f;
                float x2 = (e0 + 2 < n) ? r[e0 + 2] : 0.f;
                float x3 = (e0 + 3 < n) ? r[e0 + 3] : 0.f;

                s += (x0 + x1) + (x2 + x3);
                q = fmaf(x0, x0, q); q = fmaf(x1, x1, q);
                q = fmaf(x2, x2, q); q = fmaf(x3, x3, q);

                float rp0 = __shfl_up_sync(FULLMASK, x3, 1);
                if (lane == 0) rp0 = rlast;

                float c0, c1, c2, c3;
                { float t = rp0; float cf = (t < 0.f) ? ag : alpha; c0 = fmaf(cf * t, t, omega); }
                { float t = x0;  float cf = (t < 0.f) ? ag : alpha; c1 = fmaf(cf * t, t, omega); }
                { float t = x1;  float cf = (t < 0.f) ? ag : alpha; c2 = fmaf(cf * t, t, omega); }
                { float t = x2;  float cf = (t < 0.f) ? ag : alpha; c3 = fmaf(cf * t, t, omega); }

                float p0 = c0;
                float p1 = fmaf(bp1, p0, c1);
                float p2 = fmaf(bp1, p1, c2);
                float p3 = fmaf(bp1, p2, c3);

                float A = bp4, B = p3;
                #pragma unroll
                for (int d = 1; d < 32; d <<= 1) {
                    float Bp = __shfl_up_sync(FULLMASK, B, d);
                    float Ap = __shfl_up_sync(FULLMASK, A, d);
                    if (lane >= d) { B = fmaf(A, Bp, B); A *= Ap; }
                }
                float Bu = __shfl_up_sync(FULLMASK, B, 1);
                float Bx = (lane == 0) ? 0.f : Bu;
                float Hl = fmaf(bl4, Hc, Bx);

                float h0v = fmaf(bp1, Hl, p0);
                float h1v = fmaf(bp2, Hl, p1);
                float h2v = fmaf(b3,  Hl, p2);
                float h3v = fmaf(bp4, Hl, p3);

                if (e0 + 0 < n) { out[n + e0 + 0] = h0v; out[e0 + 0] = sqrt_approx(h0v); }
                if (e0 + 1 < n) { out[n + e0 + 1] = h1v; out[e0 + 1] = sqrt_approx(h1v); }
                if (e0 + 2 < n) { out[n + e0 + 2] = h2v; out[e0 + 2] = sqrt_approx(h2v); }
                if (e0 + 3 < n) { out[n + e0 + 3] = h3v; out[e0 + 3] = sqrt_approx(h3v); }

                Hc    = __shfl_sync(FULLMASK, h3v, 31);
                rlast = __shfl_sync(FULLMASK, x3, 31);
            }
        }
    }

    // ---- block reduction of variance partials ----
    #pragma unroll
    for (int d = 16; d; d >>= 1) {
        s += __shfl_xor_sync(FULLMASK, s, d);
        q += __shfl_xor_sync(FULLMASK, q, d);
    }
    __shared__ float rs[WPB], rq[WPB];
    __shared__ bool  sLast;
    if (lane == 0) { rs[w] = s; rq[w] = q; }
    __syncthreads();
    if (tid == 0) {
        float S = 0.f, Q = 0.f;
        #pragma unroll
        for (int i = 0; i < WPB; i++) { S += rs[i]; Q += rq[i]; }
        g_ps[blockIdx.x] = S;
        g_pq[blockIdx.x] = Q;
    }
    __threadfence();
    __syncthreads();
    if (tid == 0) {
        unsigned c = atomicAdd(&g_done, 1u);
        sLast = (c == gridDim.x - 1);
    }
    __syncthreads();

    // ---- last block: fold partials -> h0, fixup outputs [0,1024) ----
    if (sLast) {
        __threadfence();
        __shared__ double ss[TPB], sq2[TPB];
        __shared__ float  sh0;
        const int nb = gridDim.x;
        double ds = 0.0, dq = 0.0;
        for (int i = tid; i < nb; i += TPB) {
            ds += (double)g_ps[i];
            dq += (double)g_pq[i];
        }
        ss[tid] = ds; sq2[tid] = dq;
        __syncthreads();
        for (int ofs = TPB / 2; ofs; ofs >>= 1) {
            if (tid < ofs) { ss[tid] += ss[tid + ofs]; sq2[tid] += sq2[tid + ofs]; }
            __syncthreads();
        }
        if (tid == 0) {
            double S = ss[0], Q = sq2[0];
            sh0 = (float)((Q - S * S / (double)n) / (double)(n - 1));
            g_done = 0;                       // reset for next graph replay
        }
        __syncthreads();

        if (tid < 32) {                       // 1 warp recomputes [0, 1024)
            const float h0 = sh0;
            const int a = lane * 32;

            float h = 0.f;
            {
                float rp = (a > 0 && a - 1 < n) ? r[a - 1] : 0.f;
                #pragma unroll
                for (int k = 0; k < 32; k++) {
                    float rv = (a + k < n) ? r[a + k] : 0.f;
                    float c;
                    if (a + k == 0) c = h0;
                    else { float cf = (rp < 0.f) ? ag : alpha; c = fmaf(cf * rp, rp, omega); }
                    h  = fmaf(beta, h, c);
                    rp = rv;
                }
            }
            float A = bp32, B = h;
            #pragma unroll
            for (int d = 1; d < 32; d <<= 1) {
                float Bp = __shfl_up_sync(FULLMASK, B, d);
                float Ap = __shfl_up_sync(FULLMASK, A, d);
                if (lane >= d) { B = fmaf(A, Bp, B); A *= Ap; }
            }
            float Bprev = __shfl_up_sync(FULLMASK, B, 1);
            float Hin = (lane == 0) ? 0.f : Bprev;

            {
                float rp = (a > 0 && a - 1 < n) ? r[a - 1] : 0.f;
                h = Hin;
                #pragma unroll
                for (int k = 0; k < 32; k++) {
                    float rv = (a + k < n) ? r[a + k] : 0.f;
                    float c;
                    if (a + k == 0) c = h0;
                    else { float cf = (rp < 0.f) ? ag : alpha; c = fmaf(cf * rp, rp, omega); }
                    h = fmaf(beta, h, c);
                    if (a + k < n) {
                        out[n + a + k] = h;
                        out[a + k]     = sqrt_approx(h);
                    }
                    rp = rv;
                }
            }
        }
    }
}

// ---------------------------------------------------------------------------
extern "C" void kernel_launch(void* const* d_in, const int* in_sizes, int n_in,
                              void* d_out, int out_size)
{
    const float* r       = (const float*)d_in[0];
    const float* p_omega = (const float*)d_in[1];
    const float* p_alpha = (const float*)d_in[2];
    const float* p_beta  = (const float*)d_in[3];
    const float* p_gamma = (const float*)d_in[4];
    const int n = in_sizes[0];

    const int nb = (n + BLK - 1) / BLK;
    k_all<<<nb, TPB>>>(r, p_omega, p_alpha, p_beta, p_gamma, (float*)d_out, n);
}

// round 13
// speedup vs baseline: 1.1115x; 1.1115x over previous
#include <cuda_runtime.h>
#include <cstdint>
#include <math.h>

// GJR-GARCH(1,1):  h[t] = c[t] + beta*h[t-1],  h[0]=var(returns,ddof=1)
// c[t] = omega + (alpha + gamma*[r[t-1]<0]) * r[t-1]^2
// Output: [sqrt(h) | h], each N floats.
//
// R12b (resubmission; R12 hit broker infra failure twice — kernel never ran):
// R5 structure with two isolated deltas:
//   (1) TPB 128 (WPB 4), CHUNK 2048 -> grid 2048 blocks, 3.46 waves (tail fix)
//   (2) plain write-back stores (no __stcs; let the 126MB L2 absorb outputs)
// Warp owns 2048 elems = 16 rounds of 128 (lane owns a float4), 4-way ILP
// groups; cross-round dependence = one fma (beta^128 carry). B-only warp scan
// with uniform step multipliers (beta^4)^d. 128-term window carry. Variance
// fused; last block folds h0 + fixes outputs [0,1024).

#define WPB   4
#define TPB   (WPB * 32)        // 128
#define CHUNK 2048
#define BLK   (WPB * CHUNK)     // 8192 elements per block
#define NPART_MAX 32768
#define FULLMASK 0xffffffffu

__device__ float    g_ps[NPART_MAX];
__device__ float    g_pq[NPART_MAX];
__device__ unsigned g_done = 0;

__device__ __forceinline__ float sqrt_approx(float x) {
    float y; asm("sqrt.approx.f32 %0, %1;" : "=f"(y) : "f"(x)); return y;
}

// exact m^e for 0<=e<=31 from precomputed squarings
__device__ __forceinline__ float powk(float m1, float m2, float m4,
                                      float m8, float m16, int e) {
    float p = 1.f;
    if (e & 1)  p *= m1;
    if (e & 2)  p *= m2;
    if (e & 4)  p *= m4;
    if (e & 8)  p *= m8;
    if (e & 16) p *= m16;
    return p;
}

__global__ void __launch_bounds__(TPB) k_all(
    const float* __restrict__ r,
    const float* __restrict__ p_omega, const float* __restrict__ p_alpha,
    const float* __restrict__ p_beta,  const float* __restrict__ p_gamma,
    float* __restrict__ out, int n)
{
    const int tid  = threadIdx.x;
    const int w    = tid >> 5;
    const int lane = tid & 31;
    const int base = blockIdx.x * BLK + w * CHUNK;

    const float omega = __ldg(p_omega);
    const float alpha = __ldg(p_alpha);
    const float beta  = __ldg(p_beta);
    const float gamma = __ldg(p_gamma);
    const float ag = alpha + gamma;

    // powers of beta with power-of-two exponents (exact squarings)
    const float bp1 = beta;
    const float bp2 = bp1 * bp1, bp4 = bp2 * bp2, bp8 = bp4 * bp4;
    const float bp16 = bp8 * bp8, bp32 = bp16 * bp16;
    const float bp64 = bp32 * bp32, bp128 = bp64 * bp64;
    const float b3 = bp1 * bp2;

    // per-lane constant: beta^(4*lane)
    const float bl4 = powk(bp4, bp8, bp16, bp32, bp64, lane);

    float s = 0.f, q = 0.f;

    if (base < n) {
        // ---- chunk carry-in Hc ~= h[base-1]: 128-term window (coalesced) ----
        float Hc = 0.f;
        if (base > 0) {
            float bj = powk(bp1, bp2, bp4, bp8, bp16, lane);   // beta^lane
            float P  = 0.f;
            const float* rb = r + base - 2 - lane;       // term j = 32*i + lane
            #pragma unroll
            for (int i = 0; i < 4; i++) {
                float rp   = rb[-32 * i];
                float coef = (rp < 0.f) ? ag : alpha;
                P  = fmaf(bj, fmaf(coef * rp, rp, omega), P);
                bj *= bp32;
            }
            #pragma unroll
            for (int d = 16; d; d >>= 1) P += __shfl_xor_sync(FULLMASK, P, d);
            Hc = P;
        }
        float rlast = (base > 0) ? __ldg(r + base - 1) : 0.f;

        if (base + CHUNK <= n && ((n & 3) == 0)) {
            // =============== fast path: 4 groups x 4 ILP rounds ===============
            const float4* r4  = (const float4*)(r + base);
            float4*       oh4 = (float4*)(out + n + base);
            float4*       os4 = (float4*)(out + base);

            #pragma unroll
            for (int g = 0; g < 4; g++) {
                float4 v[4];
                #pragma unroll
                for (int i = 0; i < 4; i++) v[i] = r4[(4 * g + i) * 32 + lane];

                // c-transform + local affine prefix; variance fused; rp0 inline
                float p0[4], p1[4], p2[4], p3[4];
                float rl_next = rlast;
                #pragma unroll
                for (int i = 0; i < 4; i++) {
                    s += (v[i].x + v[i].y) + (v[i].z + v[i].w);
                    q = fmaf(v[i].x, v[i].x, q); q = fmaf(v[i].y, v[i].y, q);
                    q = fmaf(v[i].z, v[i].z, q); q = fmaf(v[i].w, v[i].w, q);

                    float su  = __shfl_up_sync(FULLMASK, v[i].w, 1);
                    float t31 = __shfl_sync(FULLMASK, v[i].w, 31);
                    float rp0 = (lane == 0) ? rl_next : su;
                    rl_next = t31;

                    float c0, c1, c2, c3;
                    { float t = rp0;    float cf = (t < 0.f) ? ag : alpha; c0 = fmaf(cf * t, t, omega); }
                    { float t = v[i].x; float cf = (t < 0.f) ? ag : alpha; c1 = fmaf(cf * t, t, omega); }
                    { float t = v[i].y; float cf = (t < 0.f) ? ag : alpha; c2 = fmaf(cf * t, t, omega); }
                    { float t = v[i].z; float cf = (t < 0.f) ? ag : alpha; c3 = fmaf(cf * t, t, omega); }
                    p0[i] = c0;
                    p1[i] = fmaf(bp1, c0, c1);
                    p2[i] = fmaf(bp1, p1[i], c2);
                    p3[i] = fmaf(bp1, p2[i], c3);
                }
                rlast = rl_next;

                // 4 interleaved B-only warp scans; step d multiplier = (beta^4)^d
                float B[4];
                #pragma unroll
                for (int i = 0; i < 4; i++) B[i] = p3[i];
                {
                    float Bp[4];
                    #pragma unroll
                    for (int i = 0; i < 4; i++) Bp[i] = __shfl_up_sync(FULLMASK, B[i], 1);
                    #pragma unroll
                    for (int i = 0; i < 4; i++) if (lane >= 1) B[i] = fmaf(bp4, Bp[i], B[i]);
                    #pragma unroll
                    for (int i = 0; i < 4; i++) Bp[i] = __shfl_up_sync(FULLMASK, B[i], 2);
                    #pragma unroll
                    for (int i = 0; i < 4; i++) if (lane >= 2) B[i] = fmaf(bp8, Bp[i], B[i]);
                    #pragma unroll
                    for (int i = 0; i < 4; i++) Bp[i] = __shfl_up_sync(FULLMASK, B[i], 4);
                    #pragma unroll
                    for (int i = 0; i < 4; i++) if (lane >= 4) B[i] = fmaf(bp16, Bp[i], B[i]);
                    #pragma unroll
                    for (int i = 0; i < 4; i++) Bp[i] = __shfl_up_sync(FULLMASK, B[i], 8);
                    #pragma unroll
                    for (int i = 0; i < 4; i++) if (lane >= 8) B[i] = fmaf(bp32, Bp[i], B[i]);
                    #pragma unroll
                    for (int i = 0; i < 4; i++) Bp[i] = __shfl_up_sync(FULLMASK, B[i], 16);
                    #pragma unroll
                    for (int i = 0; i < 4; i++) if (lane >= 16) B[i] = fmaf(bp64, Bp[i], B[i]);
                }

                // exclusive scan value + per-round totals
                float Bx[4], T[4];
                #pragma unroll
                for (int i = 0; i < 4; i++) {
                    float bu = __shfl_up_sync(FULLMASK, B[i], 1);
                    Bx[i] = (lane == 0) ? 0.f : bu;
                    T[i]  = __shfl_sync(FULLMASK, B[i], 31);
                }

                // carry chain: one fma per round
                float Hin[4];
                Hin[0] = Hc;
                Hin[1] = fmaf(bp128, Hin[0], T[0]);
                Hin[2] = fmaf(bp128, Hin[1], T[1]);
                Hin[3] = fmaf(bp128, Hin[2], T[2]);
                Hc     = fmaf(bp128, Hin[3], T[3]);

                // apply carries + plain write-back stores
                #pragma unroll
                for (int i = 0; i < 4; i++) {
                    float Hl = fmaf(bl4, Hin[i], Bx[i]);   // h[a-1] for this lane
                    float h0v = fmaf(bp1, Hl, p0[i]);
                    float h1v = fmaf(bp2, Hl, p1[i]);
                    float h2v = fmaf(b3,  Hl, p2[i]);
                    float h3v = fmaf(bp4, Hl, p3[i]);
                    oh4[(4 * g + i) * 32 + lane] = make_float4(h0v, h1v, h2v, h3v);
                    os4[(4 * g + i) * 32 + lane] =
                        make_float4(sqrt_approx(h0v), sqrt_approx(h1v),
                                    sqrt_approx(h2v), sqrt_approx(h3v));
                }
            }
        } else {
            // =============== guarded scalar path (partial chunk) ===============
            #pragma unroll 1
            for (int j = 0; j < CHUNK / 128; j++) {
                int e0 = base + j * 128 + 4 * lane;
                float x0 = (e0 + 0 < n) ? r[e0 + 0] : 0.f;
                float x1 = (e0 + 1 < n) ? r[e0 + 1] : 0.f;
                float x2 = (e0 + 2 < n) ? r[e0 + 2] : 0.f;
                float x3 = (e0 + 3 < n) ? r[e0 + 3] : 0.f;

                s += (x0 + x1) + (x2 + x3);
                q = fmaf(x0, x0, q); q = fmaf(x1, x1, q);
                q = fmaf(x2, x2, q); q = fmaf(x3, x3, q);

                float rp0 = __shfl_up_sync(FULLMASK, x3, 1);
                if (lane == 0) rp0 = rlast;

                float c0, c1, c2, c3;
                { float t = rp0; float cf = (t < 0.f) ? ag : alpha; c0 = fmaf(cf * t, t, omega); }
                { float t = x0;  float cf = (t < 0.f) ? ag : alpha; c1 = fmaf(cf * t, t, omega); }
                { float t = x1;  float cf = (t < 0.f) ? ag : alpha; c2 = fmaf(cf * t, t, omega); }
                { float t = x2;  float cf = (t < 0.f) ? ag : alpha; c3 = fmaf(cf * t, t, omega); }

                float p0 = c0;
                float p1 = fmaf(bp1, p0, c1);
                float p2 = fmaf(bp1, p1, c2);
                float p3 = fmaf(bp1, p2, c3);

                float A = bp4, B = p3;
                #pragma unroll
                for (int d = 1; d < 32; d <<= 1) {
                    float Bp = __shfl_up_sync(FULLMASK, B, d);
                    float Ap = __shfl_up_sync(FULLMASK, A, d);
                    if (lane >= d) { B = fmaf(A, Bp, B); A *= Ap; }
                }
                float Bu = __shfl_up_sync(FULLMASK, B, 1);
                float Bx = (lane == 0) ? 0.f : Bu;
                float Hl = fmaf(bl4, Hc, Bx);

                float h0v = fmaf(bp1, Hl, p0);
                float h1v = fmaf(bp2, Hl, p1);
                float h2v = fmaf(b3,  Hl, p2);
                float h3v = fmaf(bp4, Hl, p3);

                if (e0 + 0 < n) { out[n + e0 + 0] = h0v; out[e0 + 0] = sqrt_approx(h0v); }
                if (e0 + 1 < n) { out[n + e0 + 1] = h1v; out[e0 + 1] = sqrt_approx(h1v); }
                if (e0 + 2 < n) { out[n + e0 + 2] = h2v; out[e0 + 2] = sqrt_approx(h2v); }
                if (e0 + 3 < n) { out[n + e0 + 3] = h3v; out[e0 + 3] = sqrt_approx(h3v); }

                Hc    = __shfl_sync(FULLMASK, h3v, 31);
                rlast = __shfl_sync(FULLMASK, x3, 31);
            }
        }
    }

    // ---- block reduction of variance partials ----
    #pragma unroll
    for (int d = 16; d; d >>= 1) {
        s += __shfl_xor_sync(FULLMASK, s, d);
        q += __shfl_xor_sync(FULLMASK, q, d);
    }
    __shared__ float rs[WPB], rq[WPB];
    __shared__ bool  sLast;
    if (lane == 0) { rs[w] = s; rq[w] = q; }
    __syncthreads();
    if (tid == 0) {
        float S = 0.f, Q = 0.f;
        #pragma unroll
        for (int i = 0; i < WPB; i++) { S += rs[i]; Q += rq[i]; }
        g_ps[blockIdx.x] = S;
        g_pq[blockIdx.x] = Q;
    }
    __threadfence();
    __syncthreads();
    if (tid == 0) {
        unsigned c = atomicAdd(&g_done, 1u);
        sLast = (c == gridDim.x - 1);
    }
    __syncthreads();

    // ---- last block: fold partials -> h0, fixup outputs [0,1024) ----
    if (sLast) {
        __threadfence();
        __shared__ double ss[TPB], sq2[TPB];
        __shared__ float  sh0;
        const int nb = gridDim.x;
        double ds = 0.0, dq = 0.0;
        for (int i = tid; i < nb; i += TPB) {
            ds += (double)g_ps[i];
            dq += (double)g_pq[i];
        }
        ss[tid] = ds; sq2[tid] = dq;
        __syncthreads();
        for (int ofs = TPB / 2; ofs; ofs >>= 1) {
            if (tid < ofs) { ss[tid] += ss[tid + ofs]; sq2[tid] += sq2[tid + ofs]; }
            __syncthreads();
        }
        if (tid == 0) {
            double S = ss[0], Q = sq2[0];
            sh0 = (float)((Q - S * S / (double)n) / (double)(n - 1));
            g_done = 0;                       // reset for next graph replay
        }
        __syncthreads();

        if (tid < 32) {                       // 1 warp recomputes [0, 1024)
            const float h0 = sh0;
            const int a = lane * 32;

            float h = 0.f;
            {
                float rp = (a > 0 && a - 1 < n) ? r[a - 1] : 0.f;
                #pragma unroll
                for (int k = 0; k < 32; k++) {
                    float rv = (a + k < n) ? r[a + k] : 0.f;
                    float c;
                    if (a + k == 0) c = h0;
                    else { float cf = (rp < 0.f) ? ag : alpha; c = fmaf(cf * rp, rp, omega); }
                    h  = fmaf(beta, h, c);
                    rp = rv;
                }
            }
            float A = bp32, B = h;
            #pragma unroll
            for (int d = 1; d < 32; d <<= 1) {
                float Bp = __shfl_up_sync(FULLMASK, B, d);
                float Ap = __shfl_up_sync(FULLMASK, A, d);
                if (lane >= d) { B = fmaf(A, Bp, B); A *= Ap; }
            }
            float Bprev = __shfl_up_sync(FULLMASK, B, 1);
            float Hin = (lane == 0) ? 0.f : Bprev;

            {
                float rp = (a > 0 && a - 1 < n) ? r[a - 1] : 0.f;
                h = Hin;
                #pragma unroll
                for (int k = 0; k < 32; k++) {
                    float rv = (a + k < n) ? r[a + k] : 0.f;
                    float c;
                    if (a + k == 0) c = h0;
                    else { float cf = (rp < 0.f) ? ag : alpha; c = fmaf(cf * rp, rp, omega); }
                    h = fmaf(beta, h, c);
                    if (a + k < n) {
                        out[n + a + k] = h;
                        out[a + k]     = sqrt_approx(h);
                    }
                    rp = rv;
                }
            }
        }
    }
}

// ---------------------------------------------------------------------------
extern "C" void kernel_launch(void* const* d_in, const int* in_sizes, int n_in,
                              void* d_out, int out_size)
{
    const float* r       = (const float*)d_in[0];
    const float* p_omega = (const float*)d_in[1];
    const float* p_alpha = (const float*)d_in[2];
    const float* p_beta  = (const float*)d_in[3];
    const float* p_gamma = (const float*)d_in[4];
    const int n = in_sizes[0];

    const int nb = (n + BLK - 1) / BLK;
    k_all<<<nb, TPB>>>(r, p_omega, p_alpha, p_beta, p_gamma, (float*)d_out, n);
}